// round 12
// baseline (speedup 1.0000x reference)
#include <cuda_runtime.h>
#include <cstdint>

// ============================================================================
// LSTM seq2seq (B=32, T_IN=128, T_OUT=64, H=2048, IO=1) via mma.sync tf32.
//
// R10 (resubmit after infra failure): 128 CTAs x 512 thr; 16 warps =
// (gate, k-quarter). Each warp m16 x n32 x k512 = 256 MMAs. 4 warps/SMSP
// to hide LDS/LDG latency.
// ============================================================================

#define HID 2048
#define TIN 128
#define TOUT 64
#define NCTA 128
#define ACTA_FLOATS 131072     // per CTA: 4 gates x 16 units x 2048 k
#define HSTAGE_FLOATS 65536

// dynamic smem float offsets
#define SB_F(i) ((i) * 4096)   // 8 chunk buffers (16 KB each): quarter q uses 2q, 2q+1
#define EXPB_F 32768           // partials for kq=1..3: 3 x (4 gates x 528)
#define EX_F 39104             // final gates: 4 x 528
#define SHH_F 41216            // 16 x 33
#define SFC_F 41744            // 16
#define SX_F 41760             // 32
#define SRED_F 41792           // 16 x 32 reduction scratch
#define SMEM_BYTES 169216

// ---------------- device scratch --------------------------------------------
__device__ __align__(16) float g_Aenc[(size_t)NCTA * ACTA_FLOATS];  // 64 MB
__device__ __align__(16) float g_Adec[(size_t)NCTA * ACTA_FLOATS];  // 64 MB
__device__ __align__(16) float g_hstage[2][HSTAGE_FLOATS];
__device__ __align__(16) float g_c[HID * 32];
__device__ __align__(16) float g_ypart[TOUT * NCTA * 32];

// ---------------- index maps -------------------------------------------------
__device__ __forceinline__ int frag_a16_row(int lane, int j) {
    return (lane >> 2) + 8 * (j & 1);
}
__device__ __forceinline__ int frag_a16_col(int lane, int j) {
    return (lane & 3) + 4 * ((j >> 1) & 1);
}
__device__ __forceinline__ int frag_d_row(int lane, int r) { return (lane >> 2) + 8 * (r >> 1); }
__device__ __forceinline__ int frag_d_col(int lane, int r) { return 2 * (lane & 3) + (r & 1); }
// staged-h fragment-major index for h[k][n] (k=unit, n=batch)
__device__ __forceinline__ int hidx(int k, int n) {
    return (k >> 3) * 256 + (((n & 7) << 2) | (k & 3)) * 8 + (n >> 3) * 2 + ((k >> 2) & 1);
}

// ---------------- helpers ----------------------------------------------------
__device__ __forceinline__ float to_tf32(float v) {
    uint32_t r;
    asm("cvt.rna.tf32.f32 %0, %1;" : "=r"(r) : "f"(v));
    return __uint_as_float(r);
}
__device__ __forceinline__ void mma_tf32(float* d, const uint32_t* a, const uint32_t* b) {
    asm volatile(
        "mma.sync.aligned.m16n8k8.row.col.f32.tf32.tf32.f32 "
        "{%0,%1,%2,%3}, {%4,%5,%6,%7}, {%8,%9}, {%0,%1,%2,%3};"
        : "+f"(d[0]), "+f"(d[1]), "+f"(d[2]), "+f"(d[3])
        : "r"(a[0]), "r"(a[1]), "r"(a[2]), "r"(a[3]), "r"(b[0]), "r"(b[1]));
}
__device__ __forceinline__ void cp_async16(uint32_t saddr, const void* gaddr) {
    asm volatile("cp.async.cg.shared.global [%0], [%1], 16;" :: "r"(saddr), "l"(gaddr) : "memory");
}
__device__ __forceinline__ uint32_t smem_u32(const void* p) {
    uint32_t a;
    asm("{ .reg .u64 t; cvta.to.shared.u64 t, %1; cvt.u32.u64 %0, t; }" : "=r"(a) : "l"(p));
    return a;
}

// ---------------- prep: permute W_hh into fragment-major tf32 layout --------
// per (cta,gate): 256 kb x 32 lanes x 4 regs; cta owns units [cta*16, cta*16+16)
__global__ void prep_kernel(const float* __restrict__ W, int which) {
    float* dst = which ? g_Adec : g_Aenc;
    size_t f = (size_t)blockIdx.x * 256 + threadIdx.x;
    int cta = (int)(f >> 17);
    int rem = (int)(f & 0x1FFFF);
    int g = rem >> 15;            // gate
    int kb = (rem >> 7) & 255;    // k-block of 8
    int li = rem & 127;
    int lane = li >> 2;
    int j = li & 3;
    int lr = frag_a16_row(lane, j);
    int c = frag_a16_col(lane, j);
    int grow = g * HID + cta * 16 + lr;
    int gcol = kb * 8 + c;
    dst[f] = to_tf32(W[(size_t)grow * HID + gcol]);
}

__global__ void init_kernel() {
    int i = blockIdx.x * blockDim.x + threadIdx.x;
    int n = gridDim.x * blockDim.x;
    for (int j = i; j < 2 * HSTAGE_FLOATS; j += n) ((float*)g_hstage)[j] = 0.f;
    for (int j = i; j < HID * 32; j += n) g_c[j] = 0.f;
}

__global__ void final_kernel(float* __restrict__ out, const float* __restrict__ fcb) {
    int i = blockIdx.x * blockDim.x + threadIdx.x;
    if (i < 32 * TOUT) {
        int b = i / TOUT, t = i % TOUT;
        float y = fcb[0];
        #pragma unroll 8
        for (int j = 0; j < NCTA; j++) y += g_ypart[(t * NCTA + j) * 32 + b];
        out[i] = y;
    }
}

// ---------------- per-step kernel -------------------------------------------
__global__ void __launch_bounds__(512) step_kernel(
    const float* __restrict__ x,
    const float* __restrict__ Wih_e, const float* __restrict__ b_e,
    const float* __restrict__ Wih_d, const float* __restrict__ b_d,
    const float* __restrict__ fcW, const float* __restrict__ fcb,
    int step)
{
    extern __shared__ float smem[];
    const int tid = threadIdx.x;
    const int wid = tid >> 5;
    const int lane = tid & 31;
    const int g = wid & 3;        // gate
    const int kq = wid >> 2;      // k-quarter 0..3
    const int cta = blockIdx.x;

    const bool dec = (step >= TIN);
    const int p = step & 1;
    const float* Aperm = dec ? g_Adec : g_Aenc;
    const float* Wih = dec ? Wih_d : Wih_e;
    const float* bias = dec ? b_d : b_e;
    const float* Hs = g_hstage[p];

    // ---- input vector (two-phase reduction for decoder) ----
    if (!dec) {
        if (tid < 32) smem[SX_F + tid] = x[tid * TIN + step];
    } else if (step == TIN) {
        if (tid < 32) smem[SX_F + tid] = x[tid * TIN + (TIN - 1)];
    } else {
        int pg = tid >> 5, b = tid & 31;
        int d0 = step - TIN - 1;
        float v = 0.f;
        #pragma unroll
        for (int j = 0; j < 8; j++)
            v += g_ypart[(d0 * NCTA + pg * 8 + j) * 32 + b];
        smem[SRED_F + pg * 32 + b] = v;
        __syncthreads();
        if (tid < 32) {
            float v2 = fcb[0];
            #pragma unroll
            for (int pgi = 0; pgi < 16; pgi++) v2 += smem[SRED_F + pgi * 32 + tid];
            smem[SX_F + tid] = v2;
        }
    }
    if (dec && tid >= 64 && tid < 80) smem[SFC_F + tid - 64] = fcW[cta * 16 + (tid - 64)];

    // ---- prologue: cp.async chunk 0 of every quarter (chunks 0,4,8,12) ----
    uint32_t sb_base = smem_u32(smem);
    #pragma unroll
    for (int q = 0; q < 4; q++) {
        uint32_t db = sb_base + SB_F(q * 2) * 4;
        const char* src = (const char*)(Hs + q * 4 * 4096);
        #pragma unroll
        for (int i = 0; i < 2; i++)
            cp_async16(db + (tid + i * 512) * 16, src + (tid + i * 512) * 16);
    }
    asm volatile("cp.async.commit_group;" ::: "memory");

    // per-warp A base; kb stride = 128 floats = 32 float4; quarter = +8192 floats
    const float* Aw = Aperm + ((size_t)(cta * 4 + g) << 15) + kq * 8192;
    const float4* Athr = (const float4*)(Aw + lane * 4);

    uint4 Ast[8];
    #pragma unroll
    for (int i = 0; i < 8; i++) Ast[i] = *(const uint4*)(Athr + i * 32);

    float d[4][4];
    #pragma unroll
    for (int nb = 0; nb < 4; nb++)
        #pragma unroll
        for (int r = 0; r < 4; r++) d[nb][r] = 0.f;

    // ---- mainloop: 4 iterations; quarter kq consumes chunk kq*4 + c ----
    #pragma unroll 1
    for (int c = 0; c < 4; c++) {
        asm volatile("cp.async.wait_group 0;" ::: "memory");
        __syncthreads();
        if (c + 1 < 4) {
            #pragma unroll
            for (int q = 0; q < 4; q++) {
                uint32_t db = sb_base + SB_F(q * 2 + ((c + 1) & 1)) * 4;
                const char* src = (const char*)(Hs + (q * 4 + c + 1) * 4096);
                #pragma unroll
                for (int i = 0; i < 2; i++)
                    cp_async16(db + (tid + i * 512) * 16, src + (tid + i * 512) * 16);
            }
            asm volatile("cp.async.commit_group;" ::: "memory");
        }
        const float* Bbuf = smem + SB_F(kq * 2 + (c & 1));
        #pragma unroll
        for (int kbi = 0; kbi < 16; kbi++) {
            int l = c * 16 + kbi;     // local kb within this quarter (0..63)
            uint4 B0 = *(const uint4*)(Bbuf + kbi * 256 + lane * 8);
            uint4 B1 = *(const uint4*)(Bbuf + kbi * 256 + lane * 8 + 4);
            uint32_t bf[8] = {B0.x, B0.y, B0.z, B0.w, B1.x, B1.y, B1.z, B1.w};
            int s = l & 7;
            uint32_t a0[4] = {Ast[s].x, Ast[s].y, Ast[s].z, Ast[s].w};
            #pragma unroll
            for (int nb = 0; nb < 4; nb++) mma_tf32(d[nb], a0, &bf[nb * 2]);
            if (l + 8 < 64) Ast[s] = *(const uint4*)(Athr + (l + 8) * 32);
        }
        __syncthreads();
    }

    // ---- epilogue: kq 1..3 write partials; kq 0 accumulates + bias + x ----
    if (kq > 0) {
        float* exp_ = smem + EXPB_F + (kq - 1) * 2112 + g * 528;
        #pragma unroll
        for (int r = 0; r < 4; r++) {
            int lr = frag_d_row(lane, r);
            #pragma unroll
            for (int nb = 0; nb < 4; nb++) {
                int n = nb * 8 + frag_d_col(lane, r);
                exp_[lr * 33 + n] = d[nb][r];
            }
        }
    }
    __syncthreads();
    if (kq == 0) {
        #pragma unroll
        for (int r = 0; r < 4; r++) {
            int lr = frag_d_row(lane, r);
            int grow = g * HID + cta * 16 + lr;
            float wv = Wih[grow];
            float bv = bias[grow];
            #pragma unroll
            for (int nb = 0; nb < 4; nb++) {
                int n = nb * 8 + frag_d_col(lane, r);
                float v = d[nb][r] + wv * smem[SX_F + n] + bv;
                #pragma unroll
                for (int q = 1; q < 4; q++)
                    v += smem[EXPB_F + (q - 1) * 2112 + g * 528 + lr * 33 + n];
                smem[EX_F + g * 528 + lr * 33 + n] = v;
            }
        }
    }
    __syncthreads();

    // ---- fused LSTM cell update: 512 threads x 1 element ----
    {
        int lu = tid >> 5;             // local unit 0..15
        int b = tid & 31;
        int hu = cta * 16 + lu;
        float* hnext = g_hstage[p ^ 1];
        float gi = smem[EX_F + 0 * 528 + lu * 33 + b];
        float gf = smem[EX_F + 1 * 528 + lu * 33 + b];
        float gg = smem[EX_F + 2 * 528 + lu * 33 + b];
        float go = smem[EX_F + 3 * 528 + lu * 33 + b];
        float si = 1.f / (1.f + expf(-gi));
        float sf = 1.f / (1.f + expf(-gf));
        float so = 1.f / (1.f + expf(-go));
        float cc = sf * g_c[hu * 32 + b] + si * tanhf(gg);
        g_c[hu * 32 + b] = cc;
        float hh = so * tanhf(cc);
        hnext[hidx(hu, b)] = to_tf32(hh);
        if (dec) smem[SHH_F + lu * 33 + b] = hh;
    }
    __syncthreads();

    // ---- decoder fc partial over this CTA's 16 units ----
    if (dec && tid < 32) {
        float y = 0.f;
        #pragma unroll
        for (int lu = 0; lu < 16; lu++)
            y += smem[SHH_F + lu * 33 + tid] * smem[SFC_F + lu];
        g_ypart[((step - TIN) * NCTA + cta) * 32 + tid] = y;
    }
}

// ---------------- host ------------------------------------------------------
extern "C" void kernel_launch(void* const* d_in, const int* in_sizes, int n_in,
                              void* d_out, int out_size) {
    const float *x, *eWih, *eWhh, *eb, *dWih, *dWhh, *db, *fcW, *fcb;
    if (in_sizes[0] == 4096) {
        x    = (const float*)d_in[0];
        eWih = (const float*)d_in[2];
        eWhh = (const float*)d_in[3];
        eb   = (const float*)d_in[4];
        dWih = (const float*)d_in[5];
        dWhh = (const float*)d_in[6];
        db   = (const float*)d_in[7];
        fcW  = (const float*)d_in[8];
        fcb  = (const float*)d_in[9];
    } else {
        dWhh = (const float*)d_in[0];
        dWih = (const float*)d_in[1];
        db   = (const float*)d_in[2];
        eWhh = (const float*)d_in[3];
        eWih = (const float*)d_in[4];
        eb   = (const float*)d_in[5];
        fcW  = (const float*)d_in[6];
        fcb  = (const float*)d_in[7];
        x    = (const float*)d_in[10];
    }
    float* out = (float*)d_out;

    cudaFuncSetAttribute(step_kernel, cudaFuncAttributeMaxDynamicSharedMemorySize, SMEM_BYTES);

    init_kernel<<<256, 256>>>();
    prep_kernel<<<65536, 256>>>(eWhh, 0);
    prep_kernel<<<65536, 256>>>(dWhh, 1);
    for (int s = 0; s < TIN + TOUT; s++)
        step_kernel<<<NCTA, 512, SMEM_BYTES>>>(x, eWih, eb, dWih, db, fcW, fcb, s);
    final_kernel<<<8, 256>>>(out, fcb);
}

// round 13
// speedup vs baseline: 1.8421x; 1.8421x over previous
#include <cuda_runtime.h>
#include <cuda_fp16.h>
#include <cstdint>

// ============================================================================
// LSTM seq2seq (B=32, T_IN=128, T_OUT=64, H=2048, IO=1) via mma.sync fp16.
//
// R13: weights + staged h in fp16 (10-bit mantissa == tf32 => same accuracy,
// half the bytes). mma.m16n8k16.f32.f16.f16.f32. 128 CTAs x 512 thr;
// 16 warps = (gate, k-quarter); per warp m16 x n32 x k512 = 128 MMAs.
// ============================================================================

#define HID 2048
#define TIN 128
#define TOUT 64
#define NCTA 128
#define AG_HALF 32768          // per (cta,gate): 128 kb16 x 32 lanes x 8 half
#define HSTAGE_HALF 65536      // 2048 x 32 fp16, fragment-major

// SMEM layout
#define SBB(i) ((i) * 8192)    // 8 chunk buffers, 8 KB each (bytes)
#define EXPB_F 16384           // float idx: partials kq=1..3, 3 x 2112
#define EX_F 22720             // final gates 4 x 528
#define SHH_F 24832            // 16 x 33
#define SFC_F 25360            // 16
#define SX_F 25376             // 32
#define SRED_F 25408           // 16 x 32
#define SMEM_BYTES 103680

// ---------------- device scratch --------------------------------------------
__device__ __align__(16) __half g_Aenc[(size_t)NCTA * 4 * AG_HALF];  // 32 MB
__device__ __align__(16) __half g_Adec[(size_t)NCTA * 4 * AG_HALF];  // 32 MB
__device__ __align__(16) __half g_hstage[2][HSTAGE_HALF];
__device__ __align__(16) float g_c[HID * 32];
__device__ __align__(16) float g_ypart[TOUT * NCTA * 32];

// ---------------- index maps (m16n8k16 f16 fragments) ------------------------
__device__ __forceinline__ int frag_d_row(int lane, int r) { return (lane >> 2) + 8 * (r >> 1); }
__device__ __forceinline__ int frag_d_col(int lane, int r) { return 2 * (lane & 3) + (r & 1); }
// staged-h fragment-major index (halves) for h[k][n], k=unit, n=batch:
// B frag: lane=(n&7)*4 + ((k&7)>>1), reg=(k&15)>>3, pos=k&1
__device__ __forceinline__ int hidx16(int k, int n) {
    int lane = ((n & 7) << 2) | ((k >> 1) & 3);
    return (k >> 4) * 512 + (n >> 3) * 128 + lane * 4 + ((k >> 3) & 1) * 2 + (k & 1);
}

// ---------------- helpers ----------------------------------------------------
__device__ __forceinline__ void mma_f16(float* d, const uint32_t* a, const uint32_t* b) {
    asm volatile(
        "mma.sync.aligned.m16n8k16.row.col.f32.f16.f16.f32 "
        "{%0,%1,%2,%3}, {%4,%5,%6,%7}, {%8,%9}, {%0,%1,%2,%3};"
        : "+f"(d[0]), "+f"(d[1]), "+f"(d[2]), "+f"(d[3])
        : "r"(a[0]), "r"(a[1]), "r"(a[2]), "r"(a[3]), "r"(b[0]), "r"(b[1]));
}
__device__ __forceinline__ void cp_async16(uint32_t saddr, const void* gaddr) {
    asm volatile("cp.async.cg.shared.global [%0], [%1], 16;" :: "r"(saddr), "l"(gaddr) : "memory");
}
__device__ __forceinline__ uint32_t smem_u32(const void* p) {
    uint32_t a;
    asm("{ .reg .u64 t; cvta.to.shared.u64 t, %1; cvt.u32.u64 %0, t; }" : "=r"(a) : "l"(p));
    return a;
}

// ---------------- prep: permute W_hh into fp16 fragment-major layout --------
// per (cta,gate): 128 kb16; per kb16: 32 lanes x 8 half (regs a0..a3 packed).
// e=0..7: j=e>>1 (reg), pos=e&1. row r=(lane>>2)+8*(j&1); k=2*(lane&3)+8*(j>>1)+pos.
__global__ void prep_kernel(const float* __restrict__ W, int which) {
    __half* dst = which ? g_Adec : g_Aenc;
    size_t f = (size_t)blockIdx.x * 256 + threadIdx.x;
    int cta = (int)(f >> 17);
    int rem = (int)(f & 0x1FFFF);
    int g = rem >> 15;            // gate
    int rem2 = rem & 0x7FFF;
    int kb = rem2 >> 8;           // kb16 0..127
    int li = rem2 & 255;
    int lane = li >> 3;
    int e = li & 7;
    int j = e >> 1;
    int r = (lane >> 2) + 8 * (j & 1);
    int k = 2 * (lane & 3) + 8 * (j >> 1) + (e & 1);
    int grow = g * HID + cta * 16 + r;
    int gcol = kb * 16 + k;
    dst[f] = __float2half_rn(W[(size_t)grow * HID + gcol]);
}

__global__ void init_kernel() {
    int i = blockIdx.x * blockDim.x + threadIdx.x;
    int n = gridDim.x * blockDim.x;
    for (int j = i; j < 65536; j += n) ((uint32_t*)g_hstage)[j] = 0u;
    for (int j = i; j < HID * 32; j += n) g_c[j] = 0.f;
}

__global__ void final_kernel(float* __restrict__ out, const float* __restrict__ fcb) {
    int i = blockIdx.x * blockDim.x + threadIdx.x;
    if (i < 32 * TOUT) {
        int b = i / TOUT, t = i % TOUT;
        float y = fcb[0];
        #pragma unroll 8
        for (int j = 0; j < NCTA; j++) y += g_ypart[(t * NCTA + j) * 32 + b];
        out[i] = y;
    }
}

// ---------------- per-step kernel -------------------------------------------
__global__ void __launch_bounds__(512) step_kernel(
    const float* __restrict__ x,
    const float* __restrict__ Wih_e, const float* __restrict__ b_e,
    const float* __restrict__ Wih_d, const float* __restrict__ b_d,
    const float* __restrict__ fcW, const float* __restrict__ fcb,
    int step)
{
    extern __shared__ float smem[];
    const int tid = threadIdx.x;
    const int wid = tid >> 5;
    const int lane = tid & 31;
    const int g = wid & 3;        // gate
    const int kq = wid >> 2;      // k-quarter 0..3
    const int cta = blockIdx.x;

    const bool dec = (step >= TIN);
    const int p = step & 1;
    const __half* Aperm = dec ? g_Adec : g_Aenc;
    const float* Wih = dec ? Wih_d : Wih_e;
    const float* bias = dec ? b_d : b_e;
    const __half* Hs = g_hstage[p];

    // ---- input vector (two-phase reduction for decoder) ----
    if (!dec) {
        if (tid < 32) smem[SX_F + tid] = x[tid * TIN + step];
    } else if (step == TIN) {
        if (tid < 32) smem[SX_F + tid] = x[tid * TIN + (TIN - 1)];
    } else {
        int pg = tid >> 5, b = tid & 31;
        int d0 = step - TIN - 1;
        float v = 0.f;
        #pragma unroll
        for (int j = 0; j < 8; j++)
            v += g_ypart[(d0 * NCTA + pg * 8 + j) * 32 + b];
        smem[SRED_F + pg * 32 + b] = v;
        __syncthreads();
        if (tid < 32) {
            float v2 = fcb[0];
            #pragma unroll
            for (int pgi = 0; pgi < 16; pgi++) v2 += smem[SRED_F + pgi * 32 + tid];
            smem[SX_F + tid] = v2;
        }
    }
    if (dec && tid >= 64 && tid < 80) smem[SFC_F + tid - 64] = fcW[cta * 16 + (tid - 64)];

    // ---- prologue: cp.async chunk 0 of every quarter (8 KB each) ----
    uint32_t sb_base = smem_u32(smem);
    #pragma unroll
    for (int q = 0; q < 4; q++) {
        uint32_t db = sb_base + SBB(q * 2);
        const char* src = (const char*)(Hs + q * 16384);
        cp_async16(db + tid * 16, src + tid * 16);
    }
    asm volatile("cp.async.commit_group;" ::: "memory");

    // per-warp A base; kb16 stride = 512 B = 32 float4; quarter = +8192 half
    const __half* Aw = Aperm + (size_t)(cta * 4 + g) * AG_HALF + kq * 8192;
    const float4* Athr = (const float4*)(Aw + lane * 8);

    uint4 Ast[8];
    #pragma unroll
    for (int i = 0; i < 8; i++) Ast[i] = *(const uint4*)(Athr + i * 32);

    float d[4][4];
    #pragma unroll
    for (int nb = 0; nb < 4; nb++)
        #pragma unroll
        for (int r = 0; r < 4; r++) d[nb][r] = 0.f;

    // ---- mainloop: 4 iters; quarter kq consumes chunk kq*4 + c (8 kb16) ----
    #pragma unroll 1
    for (int c = 0; c < 4; c++) {
        asm volatile("cp.async.wait_group 0;" ::: "memory");
        __syncthreads();
        if (c + 1 < 4) {
            #pragma unroll
            for (int q = 0; q < 4; q++) {
                uint32_t db = sb_base + SBB(q * 2 + ((c + 1) & 1));
                const char* src = (const char*)(Hs + (q * 4 + c + 1) * 4096);
                cp_async16(db + tid * 16, src + tid * 16);
            }
            asm volatile("cp.async.commit_group;" ::: "memory");
        }
        const __half* Bbuf = (const __half*)((const char*)smem + SBB(kq * 2 + (c & 1)));
        #pragma unroll
        for (int kbi = 0; kbi < 8; kbi++) {
            int l = c * 8 + kbi;     // local kb16 within quarter (0..31)
            int s = l & 7;
            uint32_t a0[4] = {Ast[s].x, Ast[s].y, Ast[s].z, Ast[s].w};
            #pragma unroll
            for (int nb = 0; nb < 4; nb++) {
                uint2 B0 = *(const uint2*)(Bbuf + kbi * 512 + nb * 128 + lane * 4);
                uint32_t bf[2] = {B0.x, B0.y};
                mma_f16(d[nb], a0, bf);
            }
            if (l + 8 < 32) Ast[s] = *(const uint4*)(Athr + (l + 8) * 32);
        }
        __syncthreads();
    }

    // ---- epilogue: kq 1..3 write partials; kq 0 accumulates + bias + x ----
    if (kq > 0) {
        float* exp_ = smem + EXPB_F + (kq - 1) * 2112 + g * 528;
        #pragma unroll
        for (int r = 0; r < 4; r++) {
            int lr = frag_d_row(lane, r);
            #pragma unroll
            for (int nb = 0; nb < 4; nb++) {
                int n = nb * 8 + frag_d_col(lane, r);
                exp_[lr * 33 + n] = d[nb][r];
            }
        }
    }
    __syncthreads();
    if (kq == 0) {
        #pragma unroll
        for (int r = 0; r < 4; r++) {
            int lr = frag_d_row(lane, r);
            int grow = g * HID + cta * 16 + lr;
            float wv = Wih[grow];
            float bv = bias[grow];
            #pragma unroll
            for (int nb = 0; nb < 4; nb++) {
                int n = nb * 8 + frag_d_col(lane, r);
                float v = d[nb][r] + wv * smem[SX_F + n] + bv;
                #pragma unroll
                for (int q = 1; q < 4; q++)
                    v += smem[EXPB_F + (q - 1) * 2112 + g * 528 + lr * 33 + n];
                smem[EX_F + g * 528 + lr * 33 + n] = v;
            }
        }
    }
    __syncthreads();

    // ---- fused LSTM cell update: 512 threads x 1 element ----
    {
        int lu = tid >> 5;             // local unit 0..15
        int b = tid & 31;
        int hu = cta * 16 + lu;
        __half* hnext = g_hstage[p ^ 1];
        float gi = smem[EX_F + 0 * 528 + lu * 33 + b];
        float gf = smem[EX_F + 1 * 528 + lu * 33 + b];
        float gg = smem[EX_F + 2 * 528 + lu * 33 + b];
        float go = smem[EX_F + 3 * 528 + lu * 33 + b];
        float si = 1.f / (1.f + expf(-gi));
        float sf = 1.f / (1.f + expf(-gf));
        float so = 1.f / (1.f + expf(-go));
        float cc = sf * g_c[hu * 32 + b] + si * tanhf(gg);
        g_c[hu * 32 + b] = cc;
        float hh = so * tanhf(cc);
        hnext[hidx16(hu, b)] = __float2half_rn(hh);
        if (dec) smem[SHH_F + lu * 33 + b] = hh;
    }
    __syncthreads();

    // ---- decoder fc partial over this CTA's 16 units ----
    if (dec && tid < 32) {
        float y = 0.f;
        #pragma unroll
        for (int lu = 0; lu < 16; lu++)
            y += smem[SHH_F + lu * 33 + tid] * smem[SFC_F + lu];
        g_ypart[((step - TIN) * NCTA + cta) * 32 + tid] = y;
    }
}

// ---------------- host ------------------------------------------------------
extern "C" void kernel_launch(void* const* d_in, const int* in_sizes, int n_in,
                              void* d_out, int out_size) {
    const float *x, *eWih, *eWhh, *eb, *dWih, *dWhh, *db, *fcW, *fcb;
    if (in_sizes[0] == 4096) {
        x    = (const float*)d_in[0];
        eWih = (const float*)d_in[2];
        eWhh = (const float*)d_in[3];
        eb   = (const float*)d_in[4];
        dWih = (const float*)d_in[5];
        dWhh = (const float*)d_in[6];
        db   = (const float*)d_in[7];
        fcW  = (const float*)d_in[8];
        fcb  = (const float*)d_in[9];
    } else {
        dWhh = (const float*)d_in[0];
        dWih = (const float*)d_in[1];
        db   = (const float*)d_in[2];
        eWhh = (const float*)d_in[3];
        eWih = (const float*)d_in[4];
        eb   = (const float*)d_in[5];
        fcW  = (const float*)d_in[6];
        fcb  = (const float*)d_in[7];
        x    = (const float*)d_in[10];
    }
    float* out = (float*)d_out;

    cudaFuncSetAttribute(step_kernel, cudaFuncAttributeMaxDynamicSharedMemorySize, SMEM_BYTES);

    init_kernel<<<256, 256>>>();
    prep_kernel<<<65536, 256>>>(eWhh, 0);
    prep_kernel<<<65536, 256>>>(dWhh, 1);
    for (int s = 0; s < TIN + TOUT; s++)
        step_kernel<<<NCTA, 512, SMEM_BYTES>>>(x, eWih, eb, dWih, db, fcW, fcb, s);
    final_kernel<<<8, 256>>>(out, fcb);
}